// round 6
// baseline (speedup 1.0000x reference)
#include <cuda_runtime.h>
#include <cstdint>
#include <cstddef>

// Problem constants
#define BB   64
#define TT   1000
#define DI   128
#define RR   512
#define OO   64
#define ALPHA 0.1f            // DT/TAU

// Scan layout: 16 clusters x 8 CTAs, 4 batches/cluster, 64 neurons/CTA
#define CSIZE 8
#define NCLUS 16
#define BPC   4
#define NTHR  512

// Scratch: precomputed input drive x_drive = input @ Wrx^T + bx  [B][T][RR]
__device__ float g_xd[(size_t)BB * TT * RR];   // 131 MB

__device__ __forceinline__ void ffma2(unsigned long long& acc,
                                      unsigned long long w,
                                      unsigned long long r) {
    asm("fma.rn.f32x2 %0,%1,%2,%0;" : "+l"(acc) : "l"(w), "l"(r));
}
__device__ __forceinline__ float unpack_sum(unsigned long long v) {
    unsigned lo, hi;
    asm("mov.b64 {%0,%1}, %2;" : "=r"(lo), "=r"(hi) : "l"(v));
    return __uint_as_float(lo) + __uint_as_float(hi);
}

// ---------------------------------------------------------------------------
// Generic small-N GEMM (x_drive precompute and output GEMM):
//   out[m][n0+n] = bias[n0+n] + sum_k A[m][k] * W[n0+n][k]
// ---------------------------------------------------------------------------
template<int K, int OUTSTRIDE>
__global__ void __launch_bounds__(256)
gemm_nt(const float* __restrict__ g_A,
        const float* __restrict__ g_W,
        const float* __restrict__ g_bias,
        float* __restrict__ g_out)
{
    __shared__ float As[64][36];
    __shared__ float Bs[32][64];

    const int tid = threadIdx.x;
    const int m0  = blockIdx.x * 64;
    const int n0  = blockIdx.y * 64;
    const int tx  = tid & 15;
    const int ty  = tid >> 4;

    unsigned long long acc[4][2];
    #pragma unroll
    for (int i = 0; i < 4; i++) { acc[i][0] = 0ull; acc[i][1] = 0ull; }

    for (int k0 = 0; k0 < K; k0 += 32) {
        #pragma unroll
        for (int q = 0; q < 2; q++) {
            int idx = tid * 2 + q;
            int m   = idx >> 3;
            int kq  = idx & 7;
            float4 v = *(const float4*)(g_A + (size_t)(m0 + m) * K + k0 + kq * 4);
            *(float4*)&As[m][kq * 4] = v;
        }
        #pragma unroll
        for (int q = 0; q < 2; q++) {
            int n  = tid >> 2;
            int kq = (tid & 3) * 2 + q;
            float4 v = *(const float4*)(g_W + (size_t)(n0 + n) * K + k0 + kq * 4);
            Bs[kq*4+0][n] = v.x;
            Bs[kq*4+1][n] = v.y;
            Bs[kq*4+2][n] = v.z;
            Bs[kq*4+3][n] = v.w;
        }
        __syncthreads();

        #pragma unroll
        for (int k = 0; k < 32; k++) {
            unsigned long long bp0 = *(const unsigned long long*)&Bs[k][tx * 4];
            unsigned long long bp1 = *(const unsigned long long*)&Bs[k][tx * 4 + 2];
            #pragma unroll
            for (int i = 0; i < 4; i++) {
                unsigned au = __float_as_uint(As[ty * 4 + i][k]);
                unsigned long long ap;
                asm("mov.b64 %0,{%1,%1};" : "=l"(ap) : "r"(au));
                ffma2(acc[i][0], ap, bp0);
                ffma2(acc[i][1], ap, bp1);
            }
        }
        __syncthreads();
    }

    float b0v = g_bias[n0 + tx * 4 + 0];
    float b1v = g_bias[n0 + tx * 4 + 1];
    float b2v = g_bias[n0 + tx * 4 + 2];
    float b3v = g_bias[n0 + tx * 4 + 3];
    #pragma unroll
    for (int i = 0; i < 4; i++) {
        unsigned u0, u1, u2, u3;
        asm("mov.b64 {%0,%1},%2;" : "=r"(u0), "=r"(u1) : "l"(acc[i][0]));
        asm("mov.b64 {%0,%1},%2;" : "=r"(u2), "=r"(u3) : "l"(acc[i][1]));
        float4 out = make_float4(__uint_as_float(u0) + b0v,
                                 __uint_as_float(u1) + b1v,
                                 __uint_as_float(u2) + b2v,
                                 __uint_as_float(u3) + b3v);
        *(float4*)(g_out + (size_t)(m0 + ty * 4 + i) * OUTSTRIDE + n0 + tx * 4) = out;
    }
}

// ---------------------------------------------------------------------------
// Persistent scan: one cluster = 4 batches, full T=1000 recurrence.
// CTA rank w owns neurons [64w,64w+64). Thread = (2 neurons, 32-k slice).
// Wrr slice pre-packed as f32x2 pairs in registers.
// Sync: per-CTA mbarrier (count=8), parity-phased. After snew staged +
// __syncthreads, tid<8 arrive (release.cluster) on rank tid's barrier;
// rstore STG issued after the arrive (drain overlaps wait+pull; cumulated
// only by the NEXT step's release, long drained by then). All threads
// try_wait.parity (acquire.cluster), then pull one float4 each via
// ld.shared::cluster.
// ---------------------------------------------------------------------------
__global__ void __cluster_dims__(CSIZE, 1, 1) __launch_bounds__(NTHR, 1)
ctrnn_scan(const float* __restrict__ g_br,   // [B][T][RR]
           const float* __restrict__ g_Wrr,  // [RR][RR]
           const float* __restrict__ g_r0,   // [RR]
           float* __restrict__ g_rstore)     // [B][T][RR]
{
    __shared__ __align__(16) float rbuf[BPC][RR];        //  8 KB
    __shared__ __align__(16) float pz[16][BPC][64];      // 16 KB
    __shared__ __align__(16) float snew[2][BPC][64];     //  2 KB
    __shared__ __align__(8)  unsigned long long mbar;    // cluster-phase barrier

    const int w   = blockIdx.x;      // cluster rank 0..7
    const int c   = blockIdx.y;      // cluster id 0..15
    const int tid = threadIdx.x;
    const int jp  = tid & 31;        // neuron-pair index
    const int kg  = tid >> 5;        // k-group 0..15 (32 k each)
    const int j0  = jp * 2;
    const int jg0 = w * 64 + j0;
    const int b0  = c * BPC;

    const unsigned mbar_addr = (unsigned)__cvta_generic_to_shared(&mbar);

    // ---- one-time: Wrr slice into registers as packed f32x2 pairs ----
    unsigned long long wrrp[2][16];
    #pragma unroll
    for (int jj = 0; jj < 2; jj++) {
        const ulonglong2* src =
            (const ulonglong2*)(g_Wrr + (size_t)(jg0 + jj) * RR + kg * 32);
        #pragma unroll
        for (int q = 0; q < 8; q++) {
            ulonglong2 v = src[q];
            wrrp[jj][2*q+0] = v.x;
            wrrp[jj][2*q+1] = v.y;
        }
    }

    // role indices
    const int rb = tid >> 6;          // reducer batch (tid<256)
    const int rj = tid & 63;          // reducer neuron
    const size_t rrow = ((size_t)(b0 + rb)) * TT;
    // pull indices
    const int pb    = tid >> 7;       // batch 0..3
    const int pk4   = tid & 127;      // float4 index into 512
    const int prank = pk4 >> 4;       // owning CTA rank
    const int pj4   = pk4 & 15;       // float4 within owner's 64 neurons

    // ---- init rbuf from r0; init mbarrier ----
    {
        float v = g_r0[tid];
        #pragma unroll
        for (int b = 0; b < BPC; b++) rbuf[b][tid] = v;
    }
    if (tid == 0)
        asm volatile("mbarrier.init.shared.b64 [%0], %1;"
                     :: "r"(mbar_addr), "r"(CSIZE) : "memory");
    __syncthreads();
    // publish mbarrier init cluster-wide before any remote arrive
    asm volatile("barrier.cluster.arrive.aligned;" ::: "memory");
    asm volatile("barrier.cluster.wait.aligned;"   ::: "memory");

    const ulonglong2* ru = (const ulonglong2*)rbuf;   // [b*128 + k4]

    int sb = 0;
    for (int t = 0; t < TT; t++) {
        // prefetch br[t] and xd[t] for the reduce phase
        float brv = 0.f, xdv = 0.f;
        if (tid < 256) {
            brv = g_br[(rrow + t) * RR + w * 64 + rj];
            xdv = g_xd[(rrow + t) * RR + w * 64 + rj];
        }

        // ---- main matvec: 2 neurons x 32 k x 4 batches per thread ----
        unsigned long long acc0[4] = {0ull,0ull,0ull,0ull};
        unsigned long long acc1[4] = {0ull,0ull,0ull,0ull};
        {
            const int kb = kg * 8;
            #pragma unroll
            for (int ch = 0; ch < 8; ch++) {
                #pragma unroll
                for (int b = 0; b < 4; b++) {
                    ulonglong2 rv = ru[b * 128 + kb + ch];
                    ffma2(acc0[b], wrrp[0][2*ch+0], rv.x);
                    ffma2(acc0[b], wrrp[0][2*ch+1], rv.y);
                    ffma2(acc1[b], wrrp[1][2*ch+0], rv.x);
                    ffma2(acc1[b], wrrp[1][2*ch+1], rv.y);
                }
            }
        }
        #pragma unroll
        for (int b = 0; b < 4; b++) {
            pz[kg][b][j0 + 0] = unpack_sum(acc0[b]);
            pz[kg][b][j0 + 1] = unpack_sum(acc1[b]);
        }
        __syncthreads();

        // ---- reduce 16 k-groups, fast retanh, leaky update, stage ----
        float rn = 0.f;
        if (tid < 256) {
            float s0 = 0.f, s1 = 0.f;
            #pragma unroll
            for (int g = 0; g < 16; g += 2) {
                s0 += pz[g][rb][rj];
                s1 += pz[g+1][rb][rj];
            }
            float z = xdv + s0 + s1;
            // retanh: tanh(z) = 1 - 2/(exp(2z)+1), clamped at 0
            float e = __expf(2.0f * z);
            float f = (z > 0.f) ? (1.0f - __fdividef(2.0f, e + 1.0f)) : 0.0f;
            float rold = rbuf[rb][w * 64 + rj];
            rn = fmaf(ALPHA, f + brv - rold, rold);          // r + a*(-r+f+br)
            snew[sb][rb][rj] = rn;
        }
        __syncthreads();   // all snew stores done (cta-scope visible)

        // ---- signal: one arrive per peer CTA (release at cluster scope) ----
        if (tid < CSIZE) {
            asm volatile(
                "{\n\t"
                ".reg .b32 remAddr;\n\t"
                "mapa.shared::cluster.u32 remAddr, %0, %1;\n\t"
                "mbarrier.arrive.release.cluster.shared::cluster.b64 _, [remAddr];\n\t"
                "}" :: "r"(mbar_addr), "r"(tid) : "memory");
        }
        // history write AFTER the arrive: drain overlaps wait + pull
        if (tid < 256)
            g_rstore[(rrow + t) * RR + w * 64 + rj] = rn;

        // ---- wait for all 8 slices (parity-phased) ----
        {
            const unsigned par = (unsigned)(t & 1);
            unsigned done;
            asm volatile(
                "{\n\t"
                ".reg .pred p;\n\t"
                "mbarrier.try_wait.parity.acquire.cluster.shared::cta.b64 p, [%1], %2;\n\t"
                "selp.b32 %0, 1, 0, p;\n\t"
                "}" : "=r"(done) : "r"(mbar_addr), "r"(par) : "memory");
            if (!done) {
                asm volatile(
                    "{\n\t"
                    ".reg .pred P1;\n\t"
                    "WAIT_LOOP_%=:\n\t"
                    "mbarrier.try_wait.parity.acquire.cluster.shared::cta.b64 P1, [%0], %1;\n\t"
                    "@P1 bra.uni WAIT_DONE_%=;\n\t"
                    "bra.uni WAIT_LOOP_%=;\n\t"
                    "WAIT_DONE_%=:\n\t"
                    "}" :: "r"(mbar_addr), "r"(par) : "memory");
            }
        }

        // ---- pull the full new r: one remote float4 per thread ----
        {
            unsigned laddr = (unsigned)__cvta_generic_to_shared(
                                 &snew[sb][pb][pj4 * 4]);
            unsigned raddr;
            asm("mapa.shared::cluster.u32 %0, %1, %2;"
                : "=r"(raddr) : "r"(laddr), "r"(prank));
            float x, y2, z2, w2;
            asm volatile("ld.shared::cluster.v4.f32 {%0,%1,%2,%3},[%4];"
                         : "=f"(x), "=f"(y2), "=f"(z2), "=f"(w2) : "r"(raddr));
            *(float4*)&rbuf[pb][pk4 * 4] = make_float4(x, y2, z2, w2);
        }
        __syncthreads();
        sb ^= 1;
    }
}

__global__ void ctrnn_nop() {}

// ---------------------------------------------------------------------------
// Output layout: [ y (B*T*OO) | rstore (B*T*RR) ]
// ---------------------------------------------------------------------------
extern "C" void kernel_launch(void* const* d_in, const int* in_sizes, int n_in,
                              void* d_out, int out_size)
{
    const float* input = (const float*)d_in[0];
    const float* br    = (const float*)d_in[1];
    const float* Wrx   = (const float*)d_in[2];
    const float* bx    = (const float*)d_in[3];
    const float* Wrr   = (const float*)d_in[4];
    const float* Wyr   = (const float*)d_in[5];
    const float* by    = (const float*)d_in[6];
    const float* r0    = (const float*)d_in[7];

    float* y      = (float*)d_out;
    float* rstore = (float*)d_out + (size_t)BB * TT * OO;

    float* xd = nullptr;
    cudaGetSymbolAddress((void**)&xd, g_xd);

    // 1) x_drive = input @ Wrx^T + bx   [64000 x 512], K=128
    {
        dim3 g((BB * TT) / 64, RR / 64);
        gemm_nt<DI, RR><<<g, 256>>>(input, Wrx, bx, xd);
    }
    // 2) recurrence
    {
        dim3 grid(CSIZE, NCLUS, 1);
        ctrnn_scan<<<grid, NTHR>>>(br, Wrr, r0, rstore);
    }
    // 3) y = rstore @ Wyr^T + by        [64000 x 64], K=512
    {
        dim3 g((BB * TT) / 64, OO / 64);
        gemm_nt<RR, OO><<<g, 256>>>(rstore, Wyr, by, y);
    }
    ctrnn_nop<<<1, 32>>>();
    ctrnn_nop<<<1, 32>>>();
}